// round 13
// baseline (speedup 1.0000x reference)
#include <cuda_runtime.h>
#include <cuda_fp16.h>
#include <math.h>
#include <stdint.h>

#define NTT   365
#define NG    3000
#define NXI   20
#define HD    256
#define MROWS 3072               /* padded rows */
#define NMT   24                 /* M tiles of 128 */
#define NNT   16                 /* N tiles of 64 packed cols */
#define NKC   16                 /* K chunks of 32 (K=512) */
#define ABH   4096               /* halfs per A block (8KB) */
#define BBH   2048               /* halfs per B block (4KB, single fp16) */
#define ZHN   (NMT * 8 * ABH)    /* h-half fragment pool (per parity buffer) */
#define UBN   ((size_t)NTT * NG * 256)
#define RB_PER_T 94              /* ceil(3000/32) row blocks for ubase */
#define STG_BYTES 12288          /* A 8KB + B 4KB */
#define NSTG  4
#define RED_OFF_B (NSTG * STG_BYTES)     /* 49152 */
#define YT_OFF  (RED_OFF_B + 1024)       /* yt_s[128] floats */
#define MB_OFF  (YT_OFF + 512)           /* mbar full[4] */
#define SMEM_BYTES (MB_OFF + 64)

// ---------------- persistent device globals ---------------------------------
__device__ __half g_Wp[NNT * NKC * BBH];   // fragment-ordered weights (1MB)
__device__ __half g_Zh[2 * ZHN];           // h fragments, double-buffered (3MB)
__device__ __half g_ub[UBN];               // ubase = Win_x.x + b_in, all t (561MB)
__device__ float g_bc[1024];
__device__ float g_winy[256];              // w_in[:,20]
__device__ float g_c[MROWS * HD];
__device__ float g_ypart[2][NNT * MROWS];  // parity double-buffered partial y
__device__ float g_bout;                   // copy of b_out (read in gemm prologue)

// ---------------- helpers ----------------------------------------------------
__device__ __forceinline__ float sigm(float v) { return 1.f / (1.f + __expf(-v)); }
__device__ __forceinline__ float ftanh(float v) {
    float e = __expf(2.f * v);
    return 1.f - 2.f / (e + 1.f);
}
__device__ __forceinline__ uint32_t smem_u32(const void* p) {
    uint32_t a;
    asm("{ .reg .u64 t; cvta.to.shared.u64 t, %1; cvt.u32.u64 %0, t; }" : "=r"(a) : "l"(p));
    return a;
}
__device__ __forceinline__ void mbar_init(uint32_t m, uint32_t cnt) {
    asm volatile("mbarrier.init.shared.b64 [%0], %1;" :: "r"(m), "r"(cnt) : "memory");
}
__device__ __forceinline__ void mbar_expect(uint32_t m, uint32_t b) {
    asm volatile("mbarrier.arrive.expect_tx.shared.b64 _, [%0], %1;" :: "r"(m), "r"(b) : "memory");
}
__device__ __forceinline__ void mbar_wait(uint32_t m, uint32_t ph) {
    asm volatile("{\n\t.reg .pred P;\nW1_%=:\n\t"
        "mbarrier.try_wait.parity.acquire.cta.shared::cta.b64 P, [%0], %1, 0x989680;\n\t"
        "@P bra W2_%=;\n\tbra W1_%=;\nW2_%=:\n\t}" :: "r"(m), "r"(ph) : "memory");
}
__device__ __forceinline__ void bulk_cp(uint32_t dst, const void* src, uint32_t bytes, uint32_t mbar) {
    asm volatile("cp.async.bulk.shared::cluster.global.mbarrier::complete_tx::bytes [%0], [%1], %2, [%3];"
        :: "r"(dst), "l"(src), "r"(bytes), "r"(mbar) : "memory");
}

// fp16 m16n8k16 fragment encoding (row.col), validated rounds 4-12:
//  A reg: r = (kk>=8)*2 + (row>=8); lane = (row%8)*4 + ((kk%8)>>1); slot = kk&1
//  B reg: r = kk>>3; lane = (col%8)*4 + ((kk%8)>>1); slot = kk&1
#define MMA16(d, a, b) \
    asm volatile("mma.sync.aligned.m16n8k16.row.col.f32.f16.f16.f32 " \
        "{%0,%1,%2,%3}, {%4,%5,%6,%7}, {%8,%9}, {%0,%1,%2,%3};" \
        : "+f"((d)[0]), "+f"((d)[1]), "+f"((d)[2]), "+f"((d)[3]) \
        : "r"((a).x), "r"((a).y), "r"((a).z), "r"((a).w), \
          "r"((b).x), "r"((b).y))

// ---------------- init: pack weights (single fp16) into fragment order -------
__global__ void init_kernel(const float* __restrict__ w_ih, const float* __restrict__ b_ih,
                            const float* __restrict__ w_hh, const float* __restrict__ b_hh,
                            const float* __restrict__ w_in, const float* __restrict__ b_out)
{
    int idx = blockIdx.x * blockDim.x + threadIdx.x;
    int stride = gridDim.x * blockDim.x;
    for (int i = idx; i < 512 * 1024; i += stride) {
        int k = i >> 10, P = i & 1023;
        int nC = P >> 6, Pt = P & 63;
        int wN = Pt >> 5, Pl = Pt & 31;
        int j = Pl >> 3, s = Pl & 7, q = s >> 1, e = s & 1;
        int hl = q * 2 + (j >> 1);
        int gate = (j & 1) * 2 + e;
        int hcol = nC * 16 + wN * 8 + hl;
        int row = gate * 256 + hcol;
        float val = (k < 256) ? w_ih[row * 256 + k] : w_hh[row * 256 + (k - 256)];
        int ch = k >> 5, ks = (k >> 4) & 1, kk = k & 15;
        int nt8 = Pt >> 3;
        int lane = s * 4 + ((kk & 7) >> 1);
        int u = ((ks * 8 + nt8) * 32 + lane) * 4 + (kk >> 3) * 2 + (kk & 1);
        g_Wp[(size_t)(nC * NKC + ch) * BBH + u] = __float2half_rn(val);
    }
    for (int i = idx; i < 1024; i += stride) g_bc[i] = b_ih[i] + b_hh[i];
    for (int i = idx; i < 256; i += stride) g_winy[i] = w_in[i * 21 + 20];
    if (idx == 0) g_bout = b_out[0];
    for (int i = idx; i < MROWS * HD; i += stride) g_c[i] = 0.f;
    for (int i = idx; i < NNT * MROWS; i += stride) { g_ypart[0][i] = 0.f; g_ypart[1][i] = 0.f; }
    uint32_t* zh = (uint32_t*)g_Zh;
    for (int i = idx; i < ZHN; i += stride) zh[i] = 0u;   // both parity buffers
}

// ---------------- ubase: Win_x . x + b_in for ALL timesteps ------------------
__global__ void __launch_bounds__(256) ubase_kernel(
    const float* __restrict__ x, const float* __restrict__ w_in,
    const float* __restrict__ b_in)
{
    __shared__ float wsm[256 * 21];
    __shared__ float xsm[32 * NXI];
    int b = blockIdx.x;
    int t = b / RB_PER_T, rb = b % RB_PER_T;
    int r0 = rb * 32;
    int tid = threadIdx.x;
    for (int i = tid; i < 256 * 21; i += 256) wsm[i] = w_in[i];
    for (int i = tid; i < 32 * NXI; i += 256) {
        int rr = i / NXI, d = i % NXI;
        int row = r0 + rr;
        xsm[i] = (row < NG) ? x[((size_t)t * NG + row) * NXI + d] : 0.f;
    }
    __syncthreads();
    int col = tid;
    float w[NXI];
    #pragma unroll
    for (int d = 0; d < NXI; d++) w[d] = wsm[col * 21 + d];
    float bb = b_in[col];
    #pragma unroll 2
    for (int rr = 0; rr < 32; rr++) {
        int row = r0 + rr;
        if (row >= NG) break;
        float s = bb;
        #pragma unroll
        for (int d = 0; d < NXI; d++) s = fmaf(xsm[rr * NXI + d], w[d], s);
        g_ub[((size_t)t * NG + row) * 256 + col] = __float2half_rn(s);
    }
}

// ---------------- cooperative x-fragment compute into a stage ----------------
// 256 threads: thread -> row r = tid>>1 (0..127), col half ks = tid&1 (c = ks*16+kk)
__device__ __forceinline__ void compute_x_chunk(
    char* stage, int kc, int t, int mtb, const float* yt_s)
{
    const int tid = threadIdx.x;
    const int r = tid >> 1, ks = tid & 1;
    const int gr = mtb * 128 + r;
    __half* A = (__half*)stage;
    const int m16 = r >> 4, rl = r & 15, rq = rl & 7, hf = rl >> 3;
    if (gr < NG) {
        const float yt = yt_s[r];
        const __half* up = g_ub + ((size_t)t * NG + gr) * 256 + kc * 32 + ks * 16;
        #pragma unroll
        for (int kk = 0; kk < 16; kk++) {
            float v = fmaxf(__half2float(up[kk]) + yt * g_winy[kc * 32 + ks * 16 + kk], 0.f);
            int lane = rq * 4 + ((kk & 7) >> 1);
            int reg = ((kk >> 3) << 1) + hf;
            A[((ks * 8 + m16) * 32 + lane) * 8 + reg * 2 + (kk & 1)] = __float2half_rn(v);
        }
    } else {
        #pragma unroll
        for (int kk = 0; kk < 16; kk++) {
            int lane = rq * 4 + ((kk & 7) >> 1);
            int reg = ((kk >> 3) << 1) + hf;
            A[((ks * 8 + m16) * 32 + lane) * 8 + reg * 2 + (kk & 1)] = __half(0.f);
        }
    }
}

// ---------------- fused step kernel: fillObs + x-proj + GEMM + LSTM cell -----
// grid = 384 CTAs (24 M x 16 N), 256 threads (8 warps)
__global__ void __launch_bounds__(256) gemm_kernel(int t, const float* __restrict__ y,
                                                   const float* __restrict__ w_out,
                                                   float* __restrict__ out)
{
    extern __shared__ float sm[];
    uint32_t sb = smem_u32(sm);
    const int tid = threadIdx.x, wid = tid >> 5, lane = tid & 31;
    const int warpM = wid >> 1, warpN = wid & 1;
    const int nC = blockIdx.x & 15, mtb = blockIdx.x >> 4;
    const int par = t & 1;

    float* yt_s = (float*)((char*)sm + YT_OFF);
    uint32_t mb = sb + MB_OFF;
    if (tid == 0) {
        #pragma unroll
        for (int s = 0; s < NSTG; s++) mbar_init(mb + s * 8, 1);
    }
    // prologue: yprev reduction + fillObs for this CTA's 128 rows
    if (tid < 128) {
        int gr = mtb * 128 + tid;
        float yt = 0.f;
        if (gr < NG) {
            float yprev = 0.f;
            if (t > 0) {
                #pragma unroll
                for (int n = 0; n < NNT; n++) yprev += g_ypart[par][n * MROWS + gr];
                yprev += g_bout;
                if (nC == 0) out[(size_t)(t - 1) * NG + gr] = yprev;
            }
            float yobs = y[(size_t)t * NG + gr];
            yt = (yobs == yobs) ? yobs : yprev;  // fillObs
        }
        yt_s[tid] = yt;
    }
    __syncthreads();

    const __half* Zh_rd = g_Zh + (size_t)par * ZHN + (size_t)mtb * 8 * ABH;
    const char* Wbase = (const char*)(g_Wp + (size_t)nC * NKC * BBH);

    // initial fill: chunks 0..3 (all x): B via bulk, A computed cooperatively
    if (tid == 0) {
        #pragma unroll
        for (int s = 0; s < NSTG; s++) {
            mbar_expect(mb + s * 8, 4096u);
            bulk_cp(sb + s * STG_BYTES + 8192u, Wbase + (size_t)s * 4096, 4096u, mb + s * 8);
        }
    }
    #pragma unroll
    for (int s = 0; s < NSTG; s++)
        compute_x_chunk((char*)sm + s * STG_BYTES, s, t, mtb, yt_s);
    __syncthreads();

    float acc[2][4][4];
    #pragma unroll
    for (int a = 0; a < 2; a++)
        #pragma unroll
        for (int b = 0; b < 4; b++)
            #pragma unroll
            for (int d = 0; d < 4; d++) acc[a][b][d] = 0.f;

    for (int ch = 0; ch < NKC; ch++) {
        int st = ch & (NSTG - 1);
        uint32_t ph = (uint32_t)((ch >> 2) & 1);
        mbar_wait(mb + st * 8, ph);
        const char* stg = (const char*)sm + st * STG_BYTES;

        #pragma unroll
        for (int ks = 0; ks < 2; ks++) {
            const uint4* Ap = (const uint4*)(stg + ((ks * 8 + warpM * 2) * 32 + lane) * 16);
            uint4 a[2];
            #pragma unroll
            for (int mt = 0; mt < 2; mt++) a[mt] = Ap[mt * 32];
            const uint2* Bp = (const uint2*)(stg + 8192 + ((ks * 8 + warpN * 4) * 32 + lane) * 8);
            #pragma unroll
            for (int j = 0; j < 4; j++) {
                uint2 bh = Bp[j * 32];
                #pragma unroll
                for (int mt = 0; mt < 2; mt++) MMA16(acc[mt][j], a[mt], bh);
            }
        }
        __syncthreads();
        int nx = ch + NSTG;
        if (nx < 8) {
            // x-chunk refill: compute A cooperatively, bulk B
            if (tid == 0) {
                mbar_expect(mb + st * 8, 4096u);
                bulk_cp(sb + st * STG_BYTES + 8192u, Wbase + (size_t)nx * 4096, 4096u, mb + st * 8);
            }
            compute_x_chunk((char*)sm + st * STG_BYTES, nx, t, mtb, yt_s);
        } else if (nx < NKC) {
            if (tid == 0) {
                mbar_expect(mb + st * 8, 12288u);
                uint32_t as = sb + st * STG_BYTES;
                bulk_cp(as, Zh_rd + (size_t)(nx - 8) * ABH, 8192u, mb + st * 8);
                bulk_cp(as + 8192u, Wbase + (size_t)nx * 4096, 4096u, mb + st * 8);
            }
        }
    }

    // ---- epilogue: LSTM cell; h written as next-step A fragments ------------
    const int q = lane & 3, rb = lane >> 2;
    float* red = (float*)((char*)sm + RED_OFF_B);   // [2 warpN][128 rows]
    __half* zh_w = g_Zh + (size_t)(par ^ 1) * ZHN + (size_t)(mtb * 8 + (nC >> 1)) * ABH;
    const int ksw = nC & 1;

    #pragma unroll
    for (int mt = 0; mt < 2; mt++) {
        #pragma unroll
        for (int half = 0; half < 2; half++) {
            int row_local = warpM * 32 + mt * 16 + half * 8 + rb;
            int grow = mtb * 128 + row_local;
            int hbase = nC * 16 + warpN * 8 + 2 * q;
            float2 cold = *(const float2*)&g_c[(size_t)grow * HD + hbase];
            float coldv[2] = { cold.x, cold.y };
            float cn[2], hn[2];
            float ysum = 0.f;
            #pragma unroll
            for (int jj = 0; jj < 2; jj++) {
                int hcol = hbase + jj;
                float g_i = acc[mt][jj * 2 + 0][half * 2 + 0] + g_bc[hcol];
                float g_f = acc[mt][jj * 2 + 0][half * 2 + 1] + g_bc[256 + hcol];
                float g_g = acc[mt][jj * 2 + 1][half * 2 + 0] + g_bc[512 + hcol];
                float g_o = acc[mt][jj * 2 + 1][half * 2 + 1] + g_bc[768 + hcol];
                float cc = fmaf(sigm(g_f), coldv[jj], sigm(g_i) * ftanh(g_g));
                float hh = sigm(g_o) * ftanh(cc);
                cn[jj] = cc; hn[jj] = hh;
                ysum = fmaf(hh, __ldg(w_out + hcol), ysum);
            }
            *(float2*)&g_c[(size_t)grow * HD + hbase] = make_float2(cn[0], cn[1]);
            int u0 = (((ksw * 8) + warpM * 2 + mt) * 32 + lane) * 8 + (warpN * 2 + half) * 2;
            *reinterpret_cast<__half2*>(zh_w + u0) =
                __halves2half2(__float2half_rn(hn[0]), __float2half_rn(hn[1]));
            ysum += __shfl_xor_sync(0xffffffffu, ysum, 1);
            ysum += __shfl_xor_sync(0xffffffffu, ysum, 2);
            if (q == 0) red[warpN * 128 + row_local] = ysum;
        }
    }
    __syncthreads();
    if (tid < 128) {
        float s = red[tid] + red[128 + tid];
        g_ypart[par ^ 1][nC * MROWS + mtb * 128 + tid] = s;
    }
}

// ---------------- finalize: out[NT-1] ----------------------------------------
__global__ void final_kernel(const float* __restrict__ b_out, float* __restrict__ out)
{
    int i = blockIdx.x * blockDim.x + threadIdx.x;
    if (i < NG) {
        const int pw = ((NTT - 1) & 1) ^ 1;    // parity written by last step
        float yv = b_out[0];
        #pragma unroll
        for (int n = 0; n < NNT; n++) yv += g_ypart[pw][n * MROWS + i];
        out[(size_t)(NTT - 1) * NG + i] = yv;
    }
}

// ---------------- launch ------------------------------------------------------
extern "C" void kernel_launch(void* const* d_in, const int* in_sizes, int n_in,
                              void* d_out, int out_size)
{
    const float* x     = (const float*)d_in[0];
    const float* y     = (const float*)d_in[1];
    const float* w_in  = (const float*)d_in[2];
    const float* b_in  = (const float*)d_in[3];
    const float* w_ih  = (const float*)d_in[4];
    const float* b_ih  = (const float*)d_in[5];
    const float* w_hh  = (const float*)d_in[6];
    const float* b_hh  = (const float*)d_in[7];
    const float* w_out = (const float*)d_in[8];
    const float* b_out = (const float*)d_in[9];
    float* out = (float*)d_out;
    (void)in_sizes; (void)n_in; (void)out_size;

    cudaFuncSetAttribute(gemm_kernel, cudaFuncAttributeMaxDynamicSharedMemorySize,
                         SMEM_BYTES);

    init_kernel<<<512, 256>>>(w_ih, b_ih, w_hh, b_hh, w_in, b_out);
    ubase_kernel<<<NTT * RB_PER_T, 256>>>(x, w_in, b_in);
    for (int t = 0; t < NTT; t++)
        gemm_kernel<<<NMT * NNT, 256, SMEM_BYTES>>>(t, y, w_out, out);
    final_kernel<<<(NG + 255) / 256, 256>>>(b_out, out);
}

// round 14
// speedup vs baseline: 1.2185x; 1.2185x over previous
#include <cuda_runtime.h>
#include <cuda_fp16.h>
#include <math.h>
#include <stdint.h>

#define NTT   365
#define NG    3000
#define NXI   20
#define HD    256
#define MROWS 3072               /* padded rows */
#define NMT   24                 /* M tiles of 128 */
#define NNT   16                 /* N tiles of 64 packed cols */
#define NKC   16                 /* K chunks of 32 (K=512) */
#define ABH   4096               /* halfs per A block (8KB) */
#define BBH   2048               /* halfs per B block (4KB, single fp16) */
#define ZXN   (NMT * 8 * ABH)
#define ZHN   (NMT * 8 * ABH)    /* per parity buffer */
#define UBN   ((size_t)NTT * NG * 256)
#define RB_PER_T 94
#define STG_BYTES 12288          /* A 8KB + B 4KB */
#define NSTG  6
#define RED_OFF_B (NSTG * STG_BYTES)     /* 73728 */
#define YT_OFF  (RED_OFF_B + 1024)       /* 74752 */
#define MB_OFF  (YT_OFF + 512)           /* 75264 */
#define SMEM_BYTES (MB_OFF + 64)

// ---------------- persistent device globals ---------------------------------
__device__ __half g_Wp[NNT * NKC * BBH];   // fragment-ordered weights (1MB)
__device__ __half g_Zx[ZXN];               // x0 fragments (packed in-kernel)
__device__ __half g_Zh[2 * ZHN];           // h fragments, parity buffered
__device__ __half g_ub[UBN];               // ubase = Win_x.x + b_in (561MB)
__device__ float g_bc[1024];
__device__ float g_winy[256];
__device__ float g_c[MROWS * HD];
__device__ float g_ypart[2][NNT * MROWS];  // parity double-buffered
__device__ float g_bout;
__device__ int   g_xflag[NMT * 8];         // monotonic: = t+1 when chunk packed

// ---------------- helpers ----------------------------------------------------
__device__ __forceinline__ float sigm(float v) { return 1.f / (1.f + __expf(-v)); }
__device__ __forceinline__ float ftanh(float v) {
    float e = __expf(2.f * v);
    return 1.f - 2.f / (e + 1.f);
}
__device__ __forceinline__ uint32_t smem_u32(const void* p) {
    uint32_t a;
    asm("{ .reg .u64 t; cvta.to.shared.u64 t, %1; cvt.u32.u64 %0, t; }" : "=r"(a) : "l"(p));
    return a;
}
__device__ __forceinline__ void mbar_init(uint32_t m, uint32_t cnt) {
    asm volatile("mbarrier.init.shared.b64 [%0], %1;" :: "r"(m), "r"(cnt) : "memory");
}
__device__ __forceinline__ void mbar_expect(uint32_t m, uint32_t b) {
    asm volatile("mbarrier.arrive.expect_tx.shared.b64 _, [%0], %1;" :: "r"(m), "r"(b) : "memory");
}
__device__ __forceinline__ void mbar_wait(uint32_t m, uint32_t ph) {
    asm volatile("{\n\t.reg .pred P;\nW1_%=:\n\t"
        "mbarrier.try_wait.parity.acquire.cta.shared::cta.b64 P, [%0], %1, 0x989680;\n\t"
        "@P bra W2_%=;\n\tbra W1_%=;\nW2_%=:\n\t}" :: "r"(m), "r"(ph) : "memory");
}
__device__ __forceinline__ void bulk_cp(uint32_t dst, const void* src, uint32_t bytes, uint32_t mbar) {
    asm volatile("cp.async.bulk.shared::cluster.global.mbarrier::complete_tx::bytes [%0], [%1], %2, [%3];"
        :: "r"(dst), "l"(src), "r"(bytes), "r"(mbar) : "memory");
}

// fp16 m16n8k16 fragment encoding (row.col), validated rounds 4-13
#define MMA16(d, a, b) \
    asm volatile("mma.sync.aligned.m16n8k16.row.col.f32.f16.f16.f32 " \
        "{%0,%1,%2,%3}, {%4,%5,%6,%7}, {%8,%9}, {%0,%1,%2,%3};" \
        : "+f"((d)[0]), "+f"((d)[1]), "+f"((d)[2]), "+f"((d)[3]) \
        : "r"((a).x), "r"((a).y), "r"((a).z), "r"((a).w), \
          "r"((b).x), "r"((b).y))

// ---------------- init --------------------------------------------------------
__global__ void init_kernel(const float* __restrict__ w_ih, const float* __restrict__ b_ih,
                            const float* __restrict__ w_hh, const float* __restrict__ b_hh,
                            const float* __restrict__ w_in, const float* __restrict__ b_out)
{
    int idx = blockIdx.x * blockDim.x + threadIdx.x;
    int stride = gridDim.x * blockDim.x;
    for (int i = idx; i < 512 * 1024; i += stride) {
        int k = i >> 10, P = i & 1023;
        int nC = P >> 6, Pt = P & 63;
        int wN = Pt >> 5, Pl = Pt & 31;
        int j = Pl >> 3, s = Pl & 7, q = s >> 1, e = s & 1;
        int hl = q * 2 + (j >> 1);
        int gate = (j & 1) * 2 + e;
        int hcol = nC * 16 + wN * 8 + hl;
        int row = gate * 256 + hcol;
        float val = (k < 256) ? w_ih[row * 256 + k] : w_hh[row * 256 + (k - 256)];
        int ch = k >> 5, ks = (k >> 4) & 1, kk = k & 15;
        int nt8 = Pt >> 3;
        int lane = s * 4 + ((kk & 7) >> 1);
        int u = ((ks * 8 + nt8) * 32 + lane) * 4 + (kk >> 3) * 2 + (kk & 1);
        g_Wp[(size_t)(nC * NKC + ch) * BBH + u] = __float2half_rn(val);
    }
    for (int i = idx; i < 1024; i += stride) g_bc[i] = b_ih[i] + b_hh[i];
    for (int i = idx; i < 256; i += stride) g_winy[i] = w_in[i * 21 + 20];
    if (idx == 0) g_bout = b_out[0];
    for (int i = idx; i < MROWS * HD; i += stride) g_c[i] = 0.f;
    for (int i = idx; i < NNT * MROWS; i += stride) { g_ypart[0][i] = 0.f; g_ypart[1][i] = 0.f; }
    uint32_t* zh = (uint32_t*)g_Zh;
    for (int i = idx; i < ZHN; i += stride) zh[i] = 0u;   // both parity buffers
    for (int i = idx; i < NMT * 8; i += stride) g_xflag[i] = 0;
}

// ---------------- ubase: Win_x . x + b_in for ALL timesteps ------------------
__global__ void __launch_bounds__(256) ubase_kernel(
    const float* __restrict__ x, const float* __restrict__ w_in,
    const float* __restrict__ b_in)
{
    __shared__ float wsm[256 * 21];
    __shared__ float xsm[32 * NXI];
    int b = blockIdx.x;
    int t = b / RB_PER_T, rb = b % RB_PER_T;
    int r0 = rb * 32;
    int tid = threadIdx.x;
    for (int i = tid; i < 256 * 21; i += 256) wsm[i] = w_in[i];
    for (int i = tid; i < 32 * NXI; i += 256) {
        int rr = i / NXI, d = i % NXI;
        int row = r0 + rr;
        xsm[i] = (row < NG) ? x[((size_t)t * NG + row) * NXI + d] : 0.f;
    }
    __syncthreads();
    int col = tid;
    float w[NXI];
    #pragma unroll
    for (int d = 0; d < NXI; d++) w[d] = wsm[col * 21 + d];
    float bb = b_in[col];
    #pragma unroll 2
    for (int rr = 0; rr < 32; rr++) {
        int row = r0 + rr;
        if (row >= NG) break;
        float s = bb;
        #pragma unroll
        for (int d = 0; d < NXI; d++) s = fmaf(xsm[rr * NXI + d], w[d], s);
        g_ub[((size_t)t * NG + row) * 256 + col] = __float2half_rn(s);
    }
}

// ---------------- pack one x-chunk to g_Zx (256 threads, 2 per row) ----------
__device__ __forceinline__ void pack_x_chunk(int t, int mtb, int kc, const float* yt_s)
{
    const int tid = threadIdx.x;
    const int r = tid & 127, ks = tid >> 7;     // row, col-half
    const int gr = mtb * 128 + r;
    __half* zb = g_Zx + (size_t)(mtb * 8 + kc) * ABH;
    const int m16 = r >> 4, rl = r & 15, rq = rl & 7, hf = rl >> 3;
    if (gr < NG) {
        const float yt = yt_s[r];
        const __half* up = g_ub + ((size_t)t * NG + gr) * 256 + kc * 32 + ks * 16;
        #pragma unroll
        for (int kk = 0; kk < 16; kk++) {
            float v = fmaxf(__half2float(up[kk]) + yt * g_winy[kc * 32 + ks * 16 + kk], 0.f);
            int lane = rq * 4 + ((kk & 7) >> 1);
            int reg = ((kk >> 3) << 1) + hf;
            zb[((ks * 8 + m16) * 32 + lane) * 8 + reg * 2 + (kk & 1)] = __float2half_rn(v);
        }
    } else {
        #pragma unroll
        for (int kk = 0; kk < 16; kk++) {
            int lane = rq * 4 + ((kk & 7) >> 1);
            int reg = ((kk >> 3) << 1) + hf;
            zb[((ks * 8 + m16) * 32 + lane) * 8 + reg * 2 + (kk & 1)] = __half(0.f);
        }
    }
}

// ---------------- fused step kernel ------------------------------------------
// grid = 384 CTAs (24 M x 16 N), 256 threads; chunk order h-first: (8+i)&15.
// CTAs nC<8 pack x-chunk nC once; consumers gate x refills on g_xflag.
__global__ void __launch_bounds__(256) gemm_kernel(int t, const float* __restrict__ y,
                                                   const float* __restrict__ w_out,
                                                   float* __restrict__ out)
{
    extern __shared__ float sm[];
    uint32_t sb = smem_u32(sm);
    const int tid = threadIdx.x, wid = tid >> 5, lane = tid & 31;
    const int warpM = wid >> 1, warpN = wid & 1;
    const int nC = blockIdx.x & 15, mtb = blockIdx.x >> 4;
    const int par = t & 1;

    float* yt_s = (float*)((char*)sm + YT_OFF);
    uint32_t mb = sb + MB_OFF;
    if (tid == 0) {
        #pragma unroll
        for (int s = 0; s < NSTG; s++) mbar_init(mb + s * 8, 1);
    }
    // prologue: yprev reduction + fillObs for this CTA's rows
    if (tid < 128) {
        int gr = mtb * 128 + tid;
        float yt = 0.f;
        if (gr < NG) {
            float yprev = 0.f;
            if (t > 0) {
                #pragma unroll
                for (int n = 0; n < NNT; n++) yprev += g_ypart[par][n * MROWS + gr];
                yprev += g_bout;
                if (nC == 0) out[(size_t)(t - 1) * NG + gr] = yprev;
            }
            float yobs = y[(size_t)t * NG + gr];
            yt = (yobs == yobs) ? yobs : yprev;  // fillObs
        }
        yt_s[tid] = yt;
    }
    __syncthreads();

    const __half* Zh_rd = g_Zh + (size_t)par * ZHN + (size_t)mtb * 8 * ABH;
    const __half* Zx_rd = g_Zx + (size_t)mtb * 8 * ABH;
    const char* Wbase = (const char*)(g_Wp + (size_t)nC * NKC * BBH);

    // initial fills: stages 0..5 = h-chunks 8..13 (no dependency on flags)
    if (tid == 0) {
        #pragma unroll
        for (int s = 0; s < NSTG; s++) {
            mbar_expect(mb + s * 8, STG_BYTES);
            uint32_t as = sb + s * STG_BYTES;
            bulk_cp(as, Zh_rd + (size_t)s * ABH, 8192u, mb + s * 8);
            bulk_cp(as + 8192u, Wbase + (size_t)(8 + s) * 4096, 4096u, mb + s * 8);
        }
    }

    // producers: pack this mtile's x-chunk nC (once, zero redundancy)
    if (nC < 8) {
        pack_x_chunk(t, mtb, nC, yt_s);
        __syncthreads();
        if (tid == 0) {
            __threadfence();
            atomicExch(&g_xflag[mtb * 8 + nC], t + 1);
        }
    }

    float acc[2][4][4];
    #pragma unroll
    for (int a = 0; a < 2; a++)
        #pragma unroll
        for (int b = 0; b < 4; b++)
            #pragma unroll
            for (int d = 0; d < 4; d++) acc[a][b][d] = 0.f;

    int st = 0; uint32_t ph = 0;
    for (int i = 0; i < NKC; i++) {
        mbar_wait(mb + st * 8, ph);
        const char* stg = (const char*)sm + st * STG_BYTES;

        #pragma unroll
        for (int ks = 0; ks < 2; ks++) {
            const uint4* Ap = (const uint4*)(stg + ((ks * 8 + warpM * 2) * 32 + lane) * 16);
            uint4 a[2];
            #pragma unroll
            for (int mt = 0; mt < 2; mt++) a[mt] = Ap[mt * 32];
            const uint2* Bp = (const uint2*)(stg + 8192 + ((ks * 8 + warpN * 4) * 32 + lane) * 8);
            #pragma unroll
            for (int j = 0; j < 4; j++) {
                uint2 bh = Bp[j * 32];
                #pragma unroll
                for (int mt = 0; mt < 2; mt++) MMA16(acc[mt][j], a[mt], bh);
            }
        }
        __syncthreads();
        if (tid == 0 && i + NSTG < NKC) {
            int cN = (8 + i + NSTG) & 15;       // chunk to refill
            uint32_t as = sb + st * STG_BYTES;
            if (cN >= 8) {                       // h chunk
                mbar_expect(mb + st * 8, STG_BYTES);
                bulk_cp(as, Zh_rd + (size_t)(cN - 8) * ABH, 8192u, mb + st * 8);
            } else {                             // x chunk: gate on producer flag
                volatile int* f = &g_xflag[mtb * 8 + cN];
                while (*f < t + 1) __nanosleep(32);
                mbar_expect(mb + st * 8, STG_BYTES);
                bulk_cp(as, Zx_rd + (size_t)cN * ABH, 8192u, mb + st * 8);
            }
            bulk_cp(as + 8192u, Wbase + (size_t)cN * 4096, 4096u, mb + st * 8);
        }
        if (++st == NSTG) { st = 0; ph ^= 1; }
    }

    // ---- epilogue: LSTM cell; h written as next-step A fragments ------------
    const int q = lane & 3, rb = lane >> 2;
    float* red = (float*)((char*)sm + RED_OFF_B);
    __half* zh_w = g_Zh + (size_t)(par ^ 1) * ZHN + (size_t)(mtb * 8 + (nC >> 1)) * ABH;
    const int ksw = nC & 1;

    #pragma unroll
    for (int mt = 0; mt < 2; mt++) {
        #pragma unroll
        for (int half = 0; half < 2; half++) {
            int row_local = warpM * 32 + mt * 16 + half * 8 + rb;
            int grow = mtb * 128 + row_local;
            int hbase = nC * 16 + warpN * 8 + 2 * q;
            float2 cold = *(const float2*)&g_c[(size_t)grow * HD + hbase];
            float coldv[2] = { cold.x, cold.y };
            float cn[2], hn[2];
            float ysum = 0.f;
            #pragma unroll
            for (int jj = 0; jj < 2; jj++) {
                int hcol = hbase + jj;
                float g_i = acc[mt][jj * 2 + 0][half * 2 + 0] + g_bc[hcol];
                float g_f = acc[mt][jj * 2 + 0][half * 2 + 1] + g_bc[256 + hcol];
                float g_g = acc[mt][jj * 2 + 1][half * 2 + 0] + g_bc[512 + hcol];
                float g_o = acc[mt][jj * 2 + 1][half * 2 + 1] + g_bc[768 + hcol];
                float cc = fmaf(sigm(g_f), coldv[jj], sigm(g_i) * ftanh(g_g));
                float hh = sigm(g_o) * ftanh(cc);
                cn[jj] = cc; hn[jj] = hh;
                ysum = fmaf(hh, __ldg(w_out + hcol), ysum);
            }
            *(float2*)&g_c[(size_t)grow * HD + hbase] = make_float2(cn[0], cn[1]);
            int u0 = (((ksw * 8) + warpM * 2 + mt) * 32 + lane) * 8 + (warpN * 2 + half) * 2;
            *reinterpret_cast<__half2*>(zh_w + u0) =
                __halves2half2(__float2half_rn(hn[0]), __float2half_rn(hn[1]));
            ysum += __shfl_xor_sync(0xffffffffu, ysum, 1);
            ysum += __shfl_xor_sync(0xffffffffu, ysum, 2);
            if (q == 0) red[warpN * 128 + row_local] = ysum;
        }
    }
    __syncthreads();
    if (tid < 128) {
        float s = red[tid] + red[128 + tid];
        g_ypart[par ^ 1][nC * MROWS + mtb * 128 + tid] = s;
    }
}

// ---------------- finalize: out[NT-1] ----------------------------------------
__global__ void final_kernel(const float* __restrict__ b_out, float* __restrict__ out)
{
    int i = blockIdx.x * blockDim.x + threadIdx.x;
    if (i < NG) {
        const int pw = ((NTT - 1) & 1) ^ 1;
        float yv = b_out[0];
        #pragma unroll
        for (int n = 0; n < NNT; n++) yv += g_ypart[pw][n * MROWS + i];
        out[(size_t)(NTT - 1) * NG + i] = yv;
    }
}

// ---------------- launch ------------------------------------------------------
extern "C" void kernel_launch(void* const* d_in, const int* in_sizes, int n_in,
                              void* d_out, int out_size)
{
    const float* x     = (const float*)d_in[0];
    const float* y     = (const float*)d_in[1];
    const float* w_in  = (const float*)d_in[2];
    const float* b_in  = (const float*)d_in[3];
    const float* w_ih  = (const float*)d_in[4];
    const float* b_ih  = (const float*)d_in[5];
    const float* w_hh  = (const float*)d_in[6];
    const float* b_hh  = (const float*)d_in[7];
    const float* w_out = (const float*)d_in[8];
    const float* b_out = (const float*)d_in[9];
    float* out = (float*)d_out;
    (void)in_sizes; (void)n_in; (void)out_size;

    cudaFuncSetAttribute(gemm_kernel, cudaFuncAttributeMaxDynamicSharedMemorySize,
                         SMEM_BYTES);

    init_kernel<<<512, 256>>>(w_ih, b_ih, w_hh, b_hh, w_in, b_out);
    ubase_kernel<<<NTT * RB_PER_T, 256>>>(x, w_in, b_in);
    for (int t = 0; t < NTT; t++)
        gemm_kernel<<<NMT * NNT, 256, SMEM_BYTES>>>(t, y, w_out, out);
    final_kernel<<<(NG + 255) / 256, 256>>>(b_out, out);
}

// round 15
// speedup vs baseline: 2.1953x; 1.8016x over previous
#include <cuda_runtime.h>
#include <cuda_fp16.h>
#include <math.h>
#include <stdint.h>

#define NTT   365
#define NG    3000
#define NXI   20
#define HD    256
#define MROWS 3072               /* padded rows */
#define NMT   24                 /* M tiles of 128 */
#define NNT   16                 /* N tiles of 64 packed cols */
#define NKC   16                 /* logical K chunks of 32 (K=512) */
#define NSC   8                  /* super-chunks of 64 */
#define ABH   4096               /* halfs per A block (8KB) */
#define BBH   2048               /* halfs per B block (4KB) */
#define ZXN   (NMT * 8 * ABH)
#define ZHN   (NMT * 8 * ABH)
#define UBN   ((size_t)NTT * NG * 256)
#define RB_PER_T 94
#define STG_BYTES 24576          /* A 16KB + B 8KB (K=64 super-chunk) */
#define NSTG  3
#define RED_OFF_B (NSTG * STG_BYTES)     /* 73728 */
#define MB_OFF (RED_OFF_B + 1024)        /* 74752 */
#define SMEM_BYTES (MB_OFF + 48)

// ---------------- persistent device globals ---------------------------------
__device__ __half g_Wp[NNT * NKC * BBH];   // fragment-ordered weights (1MB)
__device__ __half g_Zx[ZXN];               // x0 fragments (prep-written)
__device__ __half g_Zh[2 * ZHN];           // h fragments, parity buffered
__device__ __half g_ub[UBN];               // ubase = Win_x.x + b_in (561MB)
__device__ float g_bc[1024];
__device__ float g_winy[256];
__device__ float g_c[MROWS * HD];
__device__ float g_ypart[NNT * MROWS];

// ---------------- helpers ----------------------------------------------------
__device__ __forceinline__ float sigm(float v) { return 1.f / (1.f + __expf(-v)); }
__device__ __forceinline__ float ftanh(float v) {
    float e = __expf(2.f * v);
    return 1.f - 2.f / (e + 1.f);
}
__device__ __forceinline__ uint32_t smem_u32(const void* p) {
    uint32_t a;
    asm("{ .reg .u64 t; cvta.to.shared.u64 t, %1; cvt.u32.u64 %0, t; }" : "=r"(a) : "l"(p));
    return a;
}
__device__ __forceinline__ void mbar_init(uint32_t m, uint32_t cnt) {
    asm volatile("mbarrier.init.shared.b64 [%0], %1;" :: "r"(m), "r"(cnt) : "memory");
}
__device__ __forceinline__ void mbar_expect(uint32_t m, uint32_t b) {
    asm volatile("mbarrier.arrive.expect_tx.shared.b64 _, [%0], %1;" :: "r"(m), "r"(b) : "memory");
}
__device__ __forceinline__ void mbar_wait(uint32_t m, uint32_t ph) {
    asm volatile("{\n\t.reg .pred P;\nW1_%=:\n\t"
        "mbarrier.try_wait.parity.acquire.cta.shared::cta.b64 P, [%0], %1, 0x989680;\n\t"
        "@P bra W2_%=;\n\tbra W1_%=;\nW2_%=:\n\t}" :: "r"(m), "r"(ph) : "memory");
}
__device__ __forceinline__ void bulk_cp(uint32_t dst, const void* src, uint32_t bytes, uint32_t mbar) {
    asm volatile("cp.async.bulk.shared::cluster.global.mbarrier::complete_tx::bytes [%0], [%1], %2, [%3];"
        :: "r"(dst), "l"(src), "r"(bytes), "r"(mbar) : "memory");
}

// fp16 m16n8k16 fragment encoding (row.col), validated rounds 4-14
#define MMA16(d, a, b) \
    asm volatile("mma.sync.aligned.m16n8k16.row.col.f32.f16.f16.f32 " \
        "{%0,%1,%2,%3}, {%4,%5,%6,%7}, {%8,%9}, {%0,%1,%2,%3};" \
        : "+f"((d)[0]), "+f"((d)[1]), "+f"((d)[2]), "+f"((d)[3]) \
        : "r"((a).x), "r"((a).y), "r"((a).z), "r"((a).w), \
          "r"((b).x), "r"((b).y))

// ---------------- init: pack weights (single fp16) into fragment order -------
__global__ void init_kernel(const float* __restrict__ w_ih, const float* __restrict__ b_ih,
                            const float* __restrict__ w_hh, const float* __restrict__ b_hh,
                            const float* __restrict__ w_in)
{
    int idx = blockIdx.x * blockDim.x + threadIdx.x;
    int stride = gridDim.x * blockDim.x;
    for (int i = idx; i < 512 * 1024; i += stride) {
        int k = i >> 10, P = i & 1023;
        int nC = P >> 6, Pt = P & 63;
        int wN = Pt >> 5, Pl = Pt & 31;
        int j = Pl >> 3, s = Pl & 7, q = s >> 1, e = s & 1;
        int hl = q * 2 + (j >> 1);
        int gate = (j & 1) * 2 + e;
        int hcol = nC * 16 + wN * 8 + hl;
        int row = gate * 256 + hcol;
        float val = (k < 256) ? w_ih[row * 256 + k] : w_hh[row * 256 + (k - 256)];
        int ch = k >> 5, ks = (k >> 4) & 1, kk = k & 15;
        int nt8 = Pt >> 3;
        int lane = s * 4 + ((kk & 7) >> 1);
        int u = ((ks * 8 + nt8) * 32 + lane) * 4 + (kk >> 3) * 2 + (kk & 1);
        g_Wp[(size_t)(nC * NKC + ch) * BBH + u] = __float2half_rn(val);
    }
    for (int i = idx; i < 1024; i += stride) g_bc[i] = b_ih[i] + b_hh[i];
    for (int i = idx; i < 256; i += stride) g_winy[i] = w_in[i * 21 + 20];
    for (int i = idx; i < MROWS * HD; i += stride) g_c[i] = 0.f;
    for (int i = idx; i < NNT * MROWS; i += stride) g_ypart[i] = 0.f;
    uint32_t* zh = (uint32_t*)g_Zh;
    for (int i = idx; i < ZHN; i += stride) zh[i] = 0u;   // both parity buffers
}

// ---------------- ubase: Win_x . x + b_in for ALL timesteps ------------------
__global__ void __launch_bounds__(256) ubase_kernel(
    const float* __restrict__ x, const float* __restrict__ w_in,
    const float* __restrict__ b_in)
{
    __shared__ float wsm[256 * 21];
    __shared__ float xsm[32 * NXI];
    int b = blockIdx.x;
    int t = b / RB_PER_T, rb = b % RB_PER_T;
    int r0 = rb * 32;
    int tid = threadIdx.x;
    for (int i = tid; i < 256 * 21; i += 256) wsm[i] = w_in[i];
    for (int i = tid; i < 32 * NXI; i += 256) {
        int rr = i / NXI, d = i % NXI;
        int row = r0 + rr;
        xsm[i] = (row < NG) ? x[((size_t)t * NG + row) * NXI + d] : 0.f;
    }
    __syncthreads();
    int col = tid;
    float w[NXI];
    #pragma unroll
    for (int d = 0; d < NXI; d++) w[d] = wsm[col * 21 + d];
    float bb = b_in[col];
    #pragma unroll 2
    for (int rr = 0; rr < 32; rr++) {
        int row = r0 + rr;
        if (row >= NG) break;
        float s = bb;
        #pragma unroll
        for (int d = 0; d < NXI; d++) s = fmaf(xsm[rr * NXI + d], w[d], s);
        g_ub[((size_t)t * NG + row) * 256 + col] = __float2half_rn(s);
    }
}

// ---------------- prep: x0 = relu(ubase + yt*winy) as fragments (R11) --------
__global__ void __launch_bounds__(128) prep_kernel(
    int t, const float* __restrict__ y, const float* __restrict__ b_out,
    float* __restrict__ out)
{
    __shared__ __half stg[ABH];
    int mt = blockIdx.x >> 3, kc = blockIdx.x & 7;
    int r = threadIdx.x;
    int gr = mt * 128 + r;
    bool valid = gr < NG;
    float v[32];

    float yt = 0.f;
    if (valid) {
        float yprev = 0.f;
        if (t > 0) {
            #pragma unroll
            for (int n = 0; n < NNT; n++) yprev += g_ypart[n * MROWS + gr];
            yprev += b_out[0];
            if (kc == 0) out[(size_t)(t - 1) * NG + gr] = yprev;
        }
        float yobs = y[(size_t)t * NG + gr];
        yt = (yobs == yobs) ? yobs : yprev;      // fillObs
        const __half* up = g_ub + ((size_t)t * NG + gr) * 256 + kc * 32;
        #pragma unroll
        for (int c = 0; c < 32; c++)
            v[c] = fmaxf(__half2float(up[c]) + yt * g_winy[kc * 32 + c], 0.f);
    } else {
        #pragma unroll
        for (int c = 0; c < 32; c++) v[c] = 0.f;
    }

    int m16 = r >> 4, rl = r & 15, rq = rl & 7, half = rl >> 3;
    #pragma unroll
    for (int c = 0; c < 32; c++) {
        int ks = c >> 4, kk = c & 15;
        int lane = rq * 4 + ((kk & 7) >> 1);
        int reg = ((kk >> 3) << 1) + half;
        int u = ((ks * 8 + m16) * 32 + lane) * 8 + reg * 2 + (kk & 1);
        stg[u] = __float2half_rn(v[c]);
    }
    __syncthreads();
    const uint4* s4 = (const uint4*)stg;
    uint4* d4 = (uint4*)(g_Zx + (size_t)(mt * 8 + kc) * ABH);
    #pragma unroll
    for (int i = r; i < 512; i += 128) d4[i] = s4[i];
}

// ---------------- GEMM + LSTM cell: fp16 single-pass, K=64 super-chunks ------
// grid = 384 CTAs (24 M x 16 N), 256 threads (8 warps, warp 32x32)
__global__ void __launch_bounds__(256) gemm_kernel(int t, const float* __restrict__ w_out)
{
    extern __shared__ float sm[];
    uint32_t sb = smem_u32(sm);
    const int tid = threadIdx.x, wid = tid >> 5, lane = tid & 31;
    const int warpM = wid >> 1, warpN = wid & 1;
    const int nC = blockIdx.x & 15, mtb = blockIdx.x >> 4;
    const int par = t & 1;

    uint32_t mb = sb + MB_OFF;
    if (tid == 0) {
        #pragma unroll
        for (int s = 0; s < NSTG; s++) mbar_init(mb + s * 8, 1);
    }
    __syncthreads();

    const __half* Zh_rd = g_Zh + (size_t)par * ZHN + (size_t)mtb * 8 * ABH;
    const __half* Zx_rd = g_Zx + (size_t)mtb * 8 * ABH;
    const char* Wbase = (const char*)(g_Wp + (size_t)nC * NKC * BBH);

    // super-chunk sc covers logical chunks 2sc, 2sc+1 (contiguous in memory)
    if (tid == 0) {
        #pragma unroll
        for (int s = 0; s < NSTG; s++) {
            mbar_expect(mb + s * 8, STG_BYTES);
            uint32_t as = sb + s * STG_BYTES;
            const void* asrc = (s < 4) ? (const void*)(Zx_rd + (size_t)(2 * s) * ABH)
                                       : (const void*)(Zh_rd + (size_t)(2 * s - 8) * ABH);
            bulk_cp(as, asrc, 16384u, mb + s * 8);
            bulk_cp(as + 16384u, Wbase + (size_t)(2 * s) * 4096, 8192u, mb + s * 8);
        }
    }

    float acc[2][4][4];
    #pragma unroll
    for (int a = 0; a < 2; a++)
        #pragma unroll
        for (int b = 0; b < 4; b++)
            #pragma unroll
            for (int d = 0; d < 4; d++) acc[a][b][d] = 0.f;

    for (int sc = 0; sc < NSC; sc++) {
        int st = sc % NSTG;
        uint32_t ph = (uint32_t)((sc / NSTG) & 1);
        mbar_wait(mb + st * 8, ph);
        const char* stg = (const char*)sm + st * STG_BYTES;

        #pragma unroll
        for (int ks = 0; ks < 4; ks++) {               // 4 k-slices of 16
            const int blk = ks >> 1, ksl = ks & 1;
            const uint4* Ap = (const uint4*)(stg + blk * 8192 +
                                ((ksl * 8 + warpM * 2) * 32 + lane) * 16);
            uint4 a[2];
            #pragma unroll
            for (int mt = 0; mt < 2; mt++) a[mt] = Ap[mt * 32];
            const uint2* Bp = (const uint2*)(stg + 16384 + blk * 4096 +
                                ((ksl * 8 + warpN * 4) * 32 + lane) * 8);
            #pragma unroll
            for (int j = 0; j < 4; j++) {
                uint2 bh = Bp[j * 32];
                #pragma unroll
                for (int mt = 0; mt < 2; mt++) MMA16(acc[mt][j], a[mt], bh);
            }
        }
        __syncthreads();
        if (tid == 0 && sc + NSTG < NSC) {
            int nx = sc + NSTG;
            mbar_expect(mb + st * 8, STG_BYTES);
            uint32_t as = sb + st * STG_BYTES;
            const void* asrc = (nx < 4) ? (const void*)(Zx_rd + (size_t)(2 * nx) * ABH)
                                        : (const void*)(Zh_rd + (size_t)(2 * nx - 8) * ABH);
            bulk_cp(as, asrc, 16384u, mb + st * 8);
            bulk_cp(as + 16384u, Wbase + (size_t)(2 * nx) * 4096, 8192u, mb + st * 8);
        }
    }

    // ---- epilogue: LSTM cell; h written as next-step A fragments ------------
    const int q = lane & 3, rb = lane >> 2;
    float* red = (float*)((char*)sm + RED_OFF_B);   // [2 warpN][128 rows]
    __half* zh_w = g_Zh + (size_t)(par ^ 1) * ZHN + (size_t)(mtb * 8 + (nC >> 1)) * ABH;
    const int ksw = nC & 1;

    #pragma unroll
    for (int mt = 0; mt < 2; mt++) {
        #pragma unroll
        for (int half = 0; half < 2; half++) {
            int row_local = warpM * 32 + mt * 16 + half * 8 + rb;
            int grow = mtb * 128 + row_local;
            int hbase = nC * 16 + warpN * 8 + 2 * q;
            float2 cold = *(const float2*)&g_c[(size_t)grow * HD + hbase];
            float coldv[2] = { cold.x, cold.y };
            float cn[2], hn[2];
            float ysum = 0.f;
            #pragma unroll
            for (int jj = 0; jj < 2; jj++) {
                int hcol = hbase + jj;
                float g_i = acc[mt][jj * 2 + 0][half * 2 + 0] + g_bc[hcol];
                float g_f = acc[mt][jj * 2 + 0][half * 2 + 1] + g_bc[256 + hcol];
                float g_g = acc[mt][jj * 2 + 1][half * 2 + 0] + g_bc[512 + hcol];
                float g_o = acc[mt][jj * 2 + 1][half * 2 + 1] + g_bc[768 + hcol];
                float cc = fmaf(sigm(g_f), coldv[jj], sigm(g_i) * ftanh(g_g));
                float hh = sigm(g_o) * ftanh(cc);
                cn[jj] = cc; hn[jj] = hh;
                ysum = fmaf(hh, __ldg(w_out + hcol), ysum);
            }
            *(float2*)&g_c[(size_t)grow * HD + hbase] = make_float2(cn[0], cn[1]);
            int u0 = (((ksw * 8) + warpM * 2 + mt) * 32 + lane) * 8 + (warpN * 2 + half) * 2;
            *reinterpret_cast<__half2*>(zh_w + u0) =
                __halves2half2(__float2half_rn(hn[0]), __float2half_rn(hn[1]));
            ysum += __shfl_xor_sync(0xffffffffu, ysum, 1);
            ysum += __shfl_xor_sync(0xffffffffu, ysum, 2);
            if (q == 0) red[warpN * 128 + row_local] = ysum;
        }
    }
    __syncthreads();
    if (tid < 128) {
        float s = red[tid] + red[128 + tid];
        g_ypart[nC * MROWS + mtb * 128 + tid] = s;
    }
}

// ---------------- finalize: out[NT-1] ----------------------------------------
__global__ void final_kernel(const float* __restrict__ b_out, float* __restrict__ out)
{
    int i = blockIdx.x * blockDim.x + threadIdx.x;
    if (i < NG) {
        float yv = b_out[0];
        #pragma unroll
        for (int n = 0; n < NNT; n++) yv += g_ypart[n * MROWS + i];
        out[(size_t)(NTT - 1) * NG + i] = yv;
    }
}

// ---------------- launch ------------------------------------------------------
extern "C" void kernel_launch(void* const* d_in, const int* in_sizes, int n_in,
                              void* d_out, int out_size)
{
    const float* x     = (const float*)d_in[0];
    const float* y     = (const float*)d_in[1];
    const float* w_in  = (const float*)d_in[2];
    const float* b_in  = (const float*)d_in[3];
    const float* w_ih  = (const float*)d_in[4];
    const float* b_ih  = (const float*)d_in[5];
    const float* w_hh  = (const float*)d_in[6];
    const float* b_hh  = (const float*)d_in[7];
    const float* w_out = (const float*)d_in[8];
    const float* b_out = (const float*)d_in[9];
    float* out = (float*)d_out;
    (void)in_sizes; (void)n_in; (void)out_size;

    cudaFuncSetAttribute(gemm_kernel, cudaFuncAttributeMaxDynamicSharedMemorySize,
                         SMEM_BYTES);

    init_kernel<<<512, 256>>>(w_ih, b_ih, w_hh, b_hh, w_in);
    ubase_kernel<<<NTT * RB_PER_T, 256>>>(x, w_in, b_in);
    for (int t = 0; t < NTT; t++) {
        prep_kernel<<<NMT * 8, 128>>>(t, y, b_out, out);
        gemm_kernel<<<NMT * NNT, 256, SMEM_BYTES>>>(t, w_out);
    }
    final_kernel<<<(NG + 255) / 256, 256>>>(b_out, out);
}